// round 11
// baseline (speedup 1.0000x reference)
#include <cuda_runtime.h>
#include <cstdint>

// Problem constants (fixed by the reference)
#define B_ 32
#define D_ 64
#define T_ 4096
#define K_ 512
#define N_ (B_ * T_)        // 131072 tokens
#define NQ_ (B_ * D_ * T_)  // 8388608 quantized elements
#define CAP_ 24

// Scratch (device globals: no allocation allowed)
__device__ unsigned int g_maxz_bits;
__device__ unsigned int g_maxc_bits;
__device__ float        g_cbnorm[K_];
__device__ int2         g_cnsc[K_];            // (cn_int - ch, 2*ch), ch = ceil(sc/2)
__device__ __align__(16) int g_cbimg[K_ * 16];
__device__ float        g_partial[256];
__device__ unsigned int g_count;

// ---------------------------------------------------------------------------
// prep 0: global max |z|
// ---------------------------------------------------------------------------
__global__ void prep_z_kernel(const float* __restrict__ z) {
    const float4* z4 = reinterpret_cast<const float4*>(z);
    float m = 0.0f;
    for (int j = blockIdx.x * blockDim.x + threadIdx.x; j < NQ_ / 4;
         j += gridDim.x * blockDim.x) {
        float4 v = z4[j];
        m = fmaxf(m, fmaxf(fmaxf(fabsf(v.x), fabsf(v.y)),
                           fmaxf(fabsf(v.z), fabsf(v.w))));
    }
#pragma unroll
    for (int o = 16; o > 0; o >>= 1) m = fmaxf(m, __shfl_xor_sync(0xffffffffu, m, o));
    if ((threadIdx.x & 31) == 0) atomicMax(&g_maxz_bits, __float_as_uint(m));
}

// prep 1: exact norms (canonical fmaf order, proven rel_err = 0.0) + max |c|
__global__ void prep_cb1_kernel(const float* __restrict__ cb) {
    int k = blockIdx.x * blockDim.x + threadIdx.x;
    if (k < K_) {
        const float* r = cb + k * D_;
        float a = 0.0f, mx = 0.0f;
#pragma unroll
        for (int i = 0; i < D_; ++i) {
            a = fmaf(r[i], r[i], a);
            mx = fmaxf(mx, fabsf(r[i]));
        }
        g_cbnorm[k] = a;
        atomicMax(&g_maxc_bits, __float_as_uint(mx));
    }
}

// prep 2: int8 image, (cn_int - ch, 2*ch)  [bit-validated in round 10]
__global__ void prep_cb2_kernel(const float* __restrict__ cb) {
    int k = blockIdx.x * blockDim.x + threadIdx.x;
    if (k >= K_) return;
    const float maxz = __uint_as_float(g_maxz_bits);
    const float maxc = __uint_as_float(g_maxc_bits);
    const float inv_sc = (maxc > 0.0f) ? 127.0f / maxc : 0.0f;
    const float* r = cb + k * D_;
    int sa = 0;
#pragma unroll
    for (int j = 0; j < 16; ++j) {
        int b0 = min(127, max(-127, __float2int_rn(r[4 * j + 0] * inv_sc)));
        int b1 = min(127, max(-127, __float2int_rn(r[4 * j + 1] * inv_sc)));
        int b2 = min(127, max(-127, __float2int_rn(r[4 * j + 2] * inv_sc)));
        int b3 = min(127, max(-127, __float2int_rn(r[4 * j + 3] * inv_sc)));
        sa += abs(b0) + abs(b1) + abs(b2) + abs(b3);
        g_cbimg[k * 16 + j] = (b0 & 0xFF) | ((b1 & 0xFF) << 8) |
                              ((b2 & 0xFF) << 16) | ((b3 & 0xFF) << 24);
    }
    const float denom = 2.0f * (maxz * (1.0f / 127.0f)) * (maxc * (1.0f / 127.0f));
    float v = (denom > 0.0f) ? g_cbnorm[k] / denom : 0.0f;
    int cni = __float2int_rn(fminf(fmaxf(v, -2.0e9f), 2.0e9f));
    int ch  = (sa + 1) >> 1;                    // ceil(sc/2): conservative
    g_cnsc[k] = make_int2(cni - ch, 2 * ch);
}

// ---------------------------------------------------------------------------
// Exact fp32 distance from PADDED smem codebook (row stride 17 float4 units).
// Bit-identical to the proven round-0 formula.
// ---------------------------------------------------------------------------
__device__ __forceinline__ float exact_dist_sm(const float* zr, float A,
                                               const float4* __restrict__ cbf,
                                               const float* __restrict__ cnf,
                                               int k) {
    const float4* cp = cbf + k * 17;
    float s0 = 0.f, s1 = 0.f, s2 = 0.f, s3 = 0.f;
#pragma unroll
    for (int i = 0; i < 16; ++i) {
        float4 c = cp[i];
        s0 = fmaf(zr[4 * i + 0], c.x, s0);
        s1 = fmaf(zr[4 * i + 1], c.y, s1);
        s2 = fmaf(zr[4 * i + 2], c.z, s2);
        s3 = fmaf(zr[4 * i + 3], c.w, s3);
    }
    float dot = __fadd_rn(__fadd_rn(s0, s1), __fadd_rn(s2, s3));
    return __fadd_rn(__fadd_rn(A, cnf[k]), -__fmul_rn(2.0f, dot));
}

// ---------------------------------------------------------------------------
// fused VQ kernel. 512 thd, 1 token/thread, 1 block/SM, grid 256.
// ---------------------------------------------------------------------------
#define SM_IMG   0                            // 2048 int4        =  32768
#define SM_CNSC  32768                        // 512 int2         =   4096
#define SM_CNF   36864                        // 512 float        =   2048
#define SM_CBF   38912                        // 512*17 float4    = 139264  -> 178176
#define SM_CAND  178176                       // 512*24 uint16    =  24576  -> 202752
#define SM_WSUM  202752                       // 16 float         =     64
#define SM_RD    202816                       // 256 double       =   2048
#define SM_LAST  204864                       // int (+pad)       =     16
#define SM_TOT   204880

__global__ __launch_bounds__(512, 1)
void vq_kernel(const float* __restrict__ z,
               const float* __restrict__ cb,
               float* __restrict__ out_q,
               float* __restrict__ out_i,
               float* __restrict__ loss_ptr) {
    extern __shared__ char sm[];
    int4*           s_img  = reinterpret_cast<int4*>(sm + SM_IMG);
    int2*           s_cnsc = reinterpret_cast<int2*>(sm + SM_CNSC);
    float*          s_cnf  = reinterpret_cast<float*>(sm + SM_CNF);
    float4*         s_cbf  = reinterpret_cast<float4*>(sm + SM_CBF);
    unsigned short* s_cand = reinterpret_cast<unsigned short*>(sm + SM_CAND);
    float*          s_wsum = reinterpret_cast<float*>(sm + SM_WSUM);
    double*         s_rd   = reinterpret_cast<double*>(sm + SM_RD);
    int*            s_last = reinterpret_cast<int*>(sm + SM_LAST);

    const int tid  = threadIdx.x;
    const int wid  = tid >> 5;
    const int lane = tid & 31;

    // ---- stage: int8 image, (cnlo,2ch), fp32 cn, padded fp32 codebook ----
    {
        const int4* src = reinterpret_cast<const int4*>(g_cbimg);
#pragma unroll
        for (int i = tid; i < K_ * 4; i += 512) s_img[i] = src[i];
        s_cnsc[tid] = g_cnsc[tid];
        s_cnf[tid]  = g_cbnorm[tid];
        const float4* cb4 = reinterpret_cast<const float4*>(cb);
#pragma unroll
        for (int i = tid; i < K_ * 16; i += 512)
            s_cbf[(i >> 4) * 17 + (i & 15)] = cb4[i];
    }

    // ---- phase 1: stream z (low reg footprint): A canonical, zp, sabs ----
    const int n = blockIdx.x * 512 + tid;
    const size_t zoff = ((size_t)(n >> 12) << 18) + (size_t)(n & 4095);
    const float* zc = z + zoff;

    const float maxz = __uint_as_float(g_maxz_bits);
    const float inv_sz = (maxz > 0.0f) ? 127.0f / maxz : 0.0f;
    float A = 0.0f;
    int zp[16];
    int sabs = 0;
#pragma unroll
    for (int j = 0; j < 16; ++j) {
        float z0 = zc[(size_t)(4 * j + 0) << 12];
        float z1 = zc[(size_t)(4 * j + 1) << 12];
        float z2 = zc[(size_t)(4 * j + 2) << 12];
        float z3 = zc[(size_t)(4 * j + 3) << 12];
        A = fmaf(z0, z0, A);            // canonical i = 0..63 order
        A = fmaf(z1, z1, A);
        A = fmaf(z2, z2, A);
        A = fmaf(z3, z3, A);
        int b0 = min(127, max(-127, __float2int_rn(z0 * inv_sz)));
        int b1 = min(127, max(-127, __float2int_rn(z1 * inv_sz)));
        int b2 = min(127, max(-127, __float2int_rn(z2 * inv_sz)));
        int b3 = min(127, max(-127, __float2int_rn(z3 * inv_sz)));
        sabs += abs(b0) + abs(b1) + abs(b2) + abs(b3);
        zp[j] = ((-b0) & 0xFF) | (((-b1) & 0xFF) << 8) |
                (((-b2) & 0xFF) << 16) | (((-b3) & 0xFF) << 24);
    }

    // sound margin (bit-validated in round 10)
    const float maxc  = __uint_as_float(g_maxc_bits);
    const float denom = 2.0f * (maxz * (1.0f / 127.0f)) * (maxc * (1.0f / 127.0f));
    const float slack_f = (denom > 0.0f) ? 2.0e-4f / denom : 4.0e9f;
    const int   slack   = (slack_f < 1.0e9f) ? ((int)slack_f + 2) : (1 << 27);
    long long ml = (long long)sabs + 2LL * slack + 128;
    const int M = (int)((ml < (1LL << 29)) ? ml : (1LL << 29));

    __syncthreads();

    // ---- phase 2: dp4a screen (seeded accumulator) -> candidate list ----
    unsigned short* cl = s_cand + tid * CAP_;
    int cnt = 0;
    int thr = 0x7FFFFFFF;
#pragma unroll 4
    for (int k = 0; k < K_; ++k) {
        int4 c0 = s_img[4 * k + 0], c1 = s_img[4 * k + 1];
        int4 c2 = s_img[4 * k + 2], c3 = s_img[4 * k + 3];
        int2 cs = s_cnsc[k];
        int a0 = cs.x, a1 = 0, a2 = 0, a3 = 0;
        a0 = __dp4a(zp[0],  c0.x, a0);  a1 = __dp4a(zp[1],  c0.y, a1);
        a2 = __dp4a(zp[2],  c0.z, a2);  a3 = __dp4a(zp[3],  c0.w, a3);
        a0 = __dp4a(zp[4],  c1.x, a0);  a1 = __dp4a(zp[5],  c1.y, a1);
        a2 = __dp4a(zp[6],  c1.z, a2);  a3 = __dp4a(zp[7],  c1.w, a3);
        a0 = __dp4a(zp[8],  c2.x, a0);  a1 = __dp4a(zp[9],  c2.y, a1);
        a2 = __dp4a(zp[10], c2.z, a2);  a3 = __dp4a(zp[11], c2.w, a3);
        a0 = __dp4a(zp[12], c3.x, a0);  a1 = __dp4a(zp[13], c3.y, a1);
        a2 = __dp4a(zp[14], c3.z, a2);  a3 = __dp4a(zp[15], c3.w, a3);
        int s = (a0 + a1) + (a2 + a3);           // = sigma - ch (seeded)
        if (s <= thr) {
            if (cnt < CAP_) cl[cnt] = (unsigned short)k;
            ++cnt;
        }
        thr = min(thr, s + cs.y + M);
    }

    // ---- phase 3: load zr (registers now free), exact rescore from smem ----
    float zr[D_];
#pragma unroll
    for (int i = 0; i < D_; ++i) zr[i] = zc[(size_t)i << 12];

    float bd = 3.402823466e38f;
    int bestk = 0;
    if (cnt <= CAP_) {
        for (int j = 0; j < cnt; ++j) {          // ascending k: first-min ties
            int k = cl[j];
            float dd = exact_dist_sm(zr, A, s_cbf, s_cnf, k);
            if (dd < bd) { bd = dd; bestk = k; }
        }
    } else {                                      // overflow: full exact scan
        for (int k = 0; k < K_; ++k) {
            float dd = exact_dist_sm(zr, A, s_cbf, s_cnf, k);
            if (dd < bd) { bd = dd; bestk = k; }
        }
    }

    if (out_i) out_i[n] = (float)bestk;

    // ---- phase 4: quantized output (fl(z + fl(q-z))) + loss partial ----
    float acc = 0.0f;
    const float4* qr = s_cbf + bestk * 17;
    float* oq = out_q ? out_q + zoff : nullptr;
#pragma unroll
    for (int j = 0; j < 16; ++j) {
        float4 qv = qr[j];
        float d0 = __fsub_rn(qv.x, zr[4 * j + 0]);
        float d1 = __fsub_rn(qv.y, zr[4 * j + 1]);
        float d2 = __fsub_rn(qv.z, zr[4 * j + 2]);
        float d3 = __fsub_rn(qv.w, zr[4 * j + 3]);
        if (oq) {
            oq[(size_t)(4 * j + 0) << 12] = __fadd_rn(zr[4 * j + 0], d0);
            oq[(size_t)(4 * j + 1) << 12] = __fadd_rn(zr[4 * j + 1], d1);
            oq[(size_t)(4 * j + 2) << 12] = __fadd_rn(zr[4 * j + 2], d2);
            oq[(size_t)(4 * j + 3) << 12] = __fadd_rn(zr[4 * j + 3], d3);
        }
        acc = fmaf(d0, d0, acc);
        acc = fmaf(d1, d1, acc);
        acc = fmaf(d2, d2, acc);
        acc = fmaf(d3, d3, acc);
    }
#pragma unroll
    for (int o = 16; o > 0; o >>= 1) acc += __shfl_xor_sync(0xffffffffu, acc, o);
    if (lane == 0) s_wsum[wid] = acc;
    __syncthreads();
    if (tid == 0) {
        float s = 0.0f;
#pragma unroll
        for (int i = 0; i < 16; ++i) s += s_wsum[i];
        g_partial[blockIdx.x] = s;
        __threadfence();
        unsigned int ticket = atomicAdd(&g_count, 1u);
        s_last[0] = (ticket == 255u) ? 1 : 0;
    }
    __syncthreads();

    // ---- last block: deterministic finalize ----
    if (s_last[0]) {
        if (tid < 256) s_rd[tid] = (double)g_partial[tid];
        __syncthreads();
        for (int st = 128; st > 0; st >>= 1) {
            if (tid < st) s_rd[tid] += s_rd[tid + st];
            __syncthreads();
        }
        if (tid == 0) {
            if (loss_ptr) {
                float cl_ = (float)(s_rd[0] / (double)NQ_);
                loss_ptr[0] = __fadd_rn(cl_, __fmul_rn(0.25f, cl_));
            }
            g_count = 0;   // reset for next graph replay
        }
    }
}

// ---------------------------------------------------------------------------
extern "C" void kernel_launch(void* const* d_in, const int* in_sizes, int n_in,
                              void* d_out, int out_size) {
    const float* z  = nullptr;
    const float* cb = nullptr;
    for (int i = 0; i < n_in; ++i) {
        if (in_sizes[i] == NQ_)          z  = (const float*)d_in[i];
        else if (in_sizes[i] == K_ * D_) cb = (const float*)d_in[i];
    }
    if (!z || !cb) return;

    float* out = (float*)d_out;
    float* loss_ptr = nullptr;
    float* q_ptr    = nullptr;
    float* i_ptr    = nullptr;

    if (out_size == 1 + NQ_ + N_) {
        loss_ptr = out; q_ptr = out + 1; i_ptr = out + 1 + NQ_;
    } else if (out_size == NQ_ + N_) {
        q_ptr = out; i_ptr = out + NQ_;
    } else if (out_size == NQ_) {
        q_ptr = out;
    } else if (out_size == N_) {
        i_ptr = out;
    } else if (out_size == 1) {
        loss_ptr = out;
    } else if (out_size > 1 + NQ_ + N_) {
        loss_ptr = out; q_ptr = out + 1; i_ptr = out + 1 + NQ_;
    }

    static bool attr_done = false;
    if (!attr_done) {
        cudaFuncSetAttribute(vq_kernel,
                             cudaFuncAttributeMaxDynamicSharedMemorySize,
                             SM_TOT);
        attr_done = true;
    }

    prep_z_kernel<<<512, 256>>>(z);
    prep_cb1_kernel<<<2, 256>>>(cb);
    prep_cb2_kernel<<<2, 256>>>(cb);
    vq_kernel<<<N_ / 512, 512, SM_TOT>>>(z, cb, q_ptr, i_ptr, loss_ptr);
}

// round 12
// speedup vs baseline: 2.8117x; 2.8117x over previous
#include <cuda_runtime.h>
#include <cstdint>

// Problem constants (fixed by the reference)
#define B_ 32
#define D_ 64
#define T_ 4096
#define K_ 512
#define N_ (B_ * T_)        // 131072 tokens
#define NQ_ (B_ * D_ * T_)  // 8388608 quantized elements

// Scratch (device globals: no allocation allowed)
__device__ unsigned int g_maxz_bits;
__device__ unsigned int g_maxc_bits;
__device__ float        g_cbnorm[K_];
__device__ int2         g_cnsc[K_];            // (cn_int - ch, 2*ch), ch = ceil(sc/2)
__device__ __align__(16) int g_cbimg[K_ * 16];
__device__ float        g_partial[256];
__device__ unsigned int g_count;

// ---------------------------------------------------------------------------
// prep 0: global max |z|
// ---------------------------------------------------------------------------
__global__ void prep_z_kernel(const float* __restrict__ z) {
    const float4* z4 = reinterpret_cast<const float4*>(z);
    float m = 0.0f;
    for (int j = blockIdx.x * blockDim.x + threadIdx.x; j < NQ_ / 4;
         j += gridDim.x * blockDim.x) {
        float4 v = z4[j];
        m = fmaxf(m, fmaxf(fmaxf(fabsf(v.x), fabsf(v.y)),
                           fmaxf(fabsf(v.z), fabsf(v.w))));
    }
#pragma unroll
    for (int o = 16; o > 0; o >>= 1) m = fmaxf(m, __shfl_xor_sync(0xffffffffu, m, o));
    if ((threadIdx.x & 31) == 0) atomicMax(&g_maxz_bits, __float_as_uint(m));
}

// prep 1: exact norms (canonical fmaf order, proven rel_err = 0.0) + max |c|
__global__ void prep_cb1_kernel(const float* __restrict__ cb) {
    int k = blockIdx.x * blockDim.x + threadIdx.x;
    if (k < K_) {
        const float* r = cb + k * D_;
        float a = 0.0f, mx = 0.0f;
#pragma unroll
        for (int i = 0; i < D_; ++i) {
            a = fmaf(r[i], r[i], a);
            mx = fmaxf(mx, fabsf(r[i]));
        }
        g_cbnorm[k] = a;
        atomicMax(&g_maxc_bits, __float_as_uint(mx));
    }
}

// prep 2: int8 image, (cn_int - ch, 2*ch)  [bit-validated rounds 10/11]
__global__ void prep_cb2_kernel(const float* __restrict__ cb) {
    int k = blockIdx.x * blockDim.x + threadIdx.x;
    if (k >= K_) return;
    const float maxz = __uint_as_float(g_maxz_bits);
    const float maxc = __uint_as_float(g_maxc_bits);
    const float inv_sc = (maxc > 0.0f) ? 127.0f / maxc : 0.0f;
    const float* r = cb + k * D_;
    int sa = 0;
#pragma unroll
    for (int j = 0; j < 16; ++j) {
        int b0 = min(127, max(-127, __float2int_rn(r[4 * j + 0] * inv_sc)));
        int b1 = min(127, max(-127, __float2int_rn(r[4 * j + 1] * inv_sc)));
        int b2 = min(127, max(-127, __float2int_rn(r[4 * j + 2] * inv_sc)));
        int b3 = min(127, max(-127, __float2int_rn(r[4 * j + 3] * inv_sc)));
        sa += abs(b0) + abs(b1) + abs(b2) + abs(b3);
        g_cbimg[k * 16 + j] = (b0 & 0xFF) | ((b1 & 0xFF) << 8) |
                              ((b2 & 0xFF) << 16) | ((b3 & 0xFF) << 24);
    }
    const float denom = 2.0f * (maxz * (1.0f / 127.0f)) * (maxc * (1.0f / 127.0f));
    float v = (denom > 0.0f) ? g_cbnorm[k] / denom : 0.0f;
    int cni = __float2int_rn(fminf(fmaxf(v, -2.0e9f), 2.0e9f));
    int ch  = (sa + 1) >> 1;                    // ceil(sc/2): conservative
    g_cnsc[k] = make_int2(cni - ch, 2 * ch);
}

// dp4a score block: s = (cn_int - ch) - idot   (seeded accumulator)
#define DP4A_SCORE(k, sOut) do {                                          \
    int4 c0 = s_img[4 * (k) + 0], c1 = s_img[4 * (k) + 1];                \
    int4 c2 = s_img[4 * (k) + 2], c3 = s_img[4 * (k) + 3];                \
    int2 cs = s_cnsc[(k)];                                                \
    int a0 = cs.x, a1 = 0, a2 = 0, a3 = 0;                                \
    a0 = __dp4a(zp[0],  c0.x, a0);  a1 = __dp4a(zp[1],  c0.y, a1);        \
    a2 = __dp4a(zp[2],  c0.z, a2);  a3 = __dp4a(zp[3],  c0.w, a3);        \
    a0 = __dp4a(zp[4],  c1.x, a0);  a1 = __dp4a(zp[5],  c1.y, a1);        \
    a2 = __dp4a(zp[6],  c1.z, a2);  a3 = __dp4a(zp[7],  c1.w, a3);        \
    a0 = __dp4a(zp[8],  c2.x, a0);  a1 = __dp4a(zp[9],  c2.y, a1);        \
    a2 = __dp4a(zp[10], c2.z, a2);  a3 = __dp4a(zp[11], c2.w, a3);        \
    a0 = __dp4a(zp[12], c3.x, a0);  a1 = __dp4a(zp[13], c3.y, a1);        \
    a2 = __dp4a(zp[14], c3.z, a2);  a3 = __dp4a(zp[15], c3.w, a3);        \
    (sOut) = (a0 + a1) + (a2 + a3);                                       \
    twoCh = cs.y;                                                         \
} while (0)

// ---------------------------------------------------------------------------
// Exact fp32 distance from PADDED smem codebook (row stride 17 float4 units).
// Bit-identical to the proven round-0 formula.
// ---------------------------------------------------------------------------
__device__ __forceinline__ float exact_dist_sm(const float* zr, float A,
                                               const float4* __restrict__ cbf,
                                               const float* __restrict__ cnf,
                                               int k) {
    const float4* cp = cbf + k * 17;
    float s0 = 0.f, s1 = 0.f, s2 = 0.f, s3 = 0.f;
#pragma unroll
    for (int i = 0; i < 16; ++i) {
        float4 c = cp[i];
        s0 = fmaf(zr[4 * i + 0], c.x, s0);
        s1 = fmaf(zr[4 * i + 1], c.y, s1);
        s2 = fmaf(zr[4 * i + 2], c.z, s2);
        s3 = fmaf(zr[4 * i + 3], c.w, s3);
    }
    float dot = __fadd_rn(__fadd_rn(s0, s1), __fadd_rn(s2, s3));
    return __fadd_rn(__fadd_rn(A, cnf[k]), -__fmul_rn(2.0f, dot));
}

// ---------------------------------------------------------------------------
// fused VQ kernel. 512 thd, 1 token/thread, 1 block/SM, grid 256.
// ---------------------------------------------------------------------------
#define SM_IMG   0                            // 2048 int4        =  32768
#define SM_CNSC  32768                        // 512 int2         =   4096
#define SM_CNF   36864                        // 512 float        =   2048
#define SM_CBF   38912                        // 512*17 float4    = 139264
#define SM_MASK  178176                       // 16*512 uint      =  32768
#define SM_WSUM  210944                       // 16 float         =     64
#define SM_RD    211008                       // 256 double       =   2048
#define SM_LAST  213056                       // int (+pad)       =     16
#define SM_TOT   213072

__global__ __launch_bounds__(512, 1)
void vq_kernel(const float* __restrict__ z,
               const float* __restrict__ cb,
               float* __restrict__ out_q,
               float* __restrict__ out_i,
               float* __restrict__ loss_ptr) {
    extern __shared__ char sm[];
    int4*     s_img  = reinterpret_cast<int4*>(sm + SM_IMG);
    int2*     s_cnsc = reinterpret_cast<int2*>(sm + SM_CNSC);
    float*    s_cnf  = reinterpret_cast<float*>(sm + SM_CNF);
    float4*   s_cbf  = reinterpret_cast<float4*>(sm + SM_CBF);
    unsigned* s_mask = reinterpret_cast<unsigned*>(sm + SM_MASK);
    float*    s_wsum = reinterpret_cast<float*>(sm + SM_WSUM);
    double*   s_rd   = reinterpret_cast<double*>(sm + SM_RD);
    int*      s_last = reinterpret_cast<int*>(sm + SM_LAST);

    const int tid  = threadIdx.x;
    const int wid  = tid >> 5;
    const int lane = tid & 31;

    // ---- stage: int8 image, (cnlo,2ch), fp32 cn, padded fp32 codebook ----
    {
        const int4* src = reinterpret_cast<const int4*>(g_cbimg);
#pragma unroll
        for (int i = tid; i < K_ * 4; i += 512) s_img[i] = src[i];
        s_cnsc[tid] = g_cnsc[tid];
        s_cnf[tid]  = g_cbnorm[tid];
        const float4* cb4 = reinterpret_cast<const float4*>(cb);
#pragma unroll
        for (int i = tid; i < K_ * 16; i += 512)
            s_cbf[(i >> 4) * 17 + (i & 15)] = cb4[i];
    }

    // ---- phase 1: stream z (low reg footprint): A canonical, zp, sabs ----
    const int n = blockIdx.x * 512 + tid;
    const size_t zoff = ((size_t)(n >> 12) << 18) + (size_t)(n & 4095);
    const float* zc = z + zoff;

    const float maxz = __uint_as_float(g_maxz_bits);
    const float inv_sz = (maxz > 0.0f) ? 127.0f / maxz : 0.0f;
    float A = 0.0f;
    int zp[16];
    int sabs = 0;
#pragma unroll
    for (int j = 0; j < 16; ++j) {
        float z0 = zc[(size_t)(4 * j + 0) << 12];
        float z1 = zc[(size_t)(4 * j + 1) << 12];
        float z2 = zc[(size_t)(4 * j + 2) << 12];
        float z3 = zc[(size_t)(4 * j + 3) << 12];
        A = fmaf(z0, z0, A);            // canonical i = 0..63 order
        A = fmaf(z1, z1, A);
        A = fmaf(z2, z2, A);
        A = fmaf(z3, z3, A);
        int b0 = min(127, max(-127, __float2int_rn(z0 * inv_sz)));
        int b1 = min(127, max(-127, __float2int_rn(z1 * inv_sz)));
        int b2 = min(127, max(-127, __float2int_rn(z2 * inv_sz)));
        int b3 = min(127, max(-127, __float2int_rn(z3 * inv_sz)));
        sabs += abs(b0) + abs(b1) + abs(b2) + abs(b3);
        zp[j] = ((-b0) & 0xFF) | (((-b1) & 0xFF) << 8) |
                (((-b2) & 0xFF) << 16) | (((-b3) & 0xFF) << 24);
    }

    // sound margin (bit-validated rounds 10/11)
    const float maxc  = __uint_as_float(g_maxc_bits);
    const float denom = 2.0f * (maxz * (1.0f / 127.0f)) * (maxc * (1.0f / 127.0f));
    const float slack_f = (denom > 0.0f) ? 2.0e-4f / denom : 4.0e9f;
    const int   slack   = (slack_f < 1.0e9f) ? ((int)slack_f + 2) : (1 << 27);
    long long ml = (long long)sabs + 2LL * slack + 128;
    const int M = (int)((ml < (1LL << 29)) ? ml : (1LL << 29));

    __syncthreads();

    // ---- phase 2a: pre-pass over 64 strided codes -> warm threshold ----
    int twoCh;
    int m0 = 0x7FFFFFFF;
#pragma unroll 4
    for (int j = 0; j < 64; ++j) {
        int s;
        DP4A_SCORE(j * 8, s);
        m0 = min(m0, s + twoCh);
    }
    int thr = m0 + M;   // thr = min over presample of (s + 2ch) + M  (sound)

    // ---- phase 2b: full dp4a screen -> candidate bitmask + word summary ----
    unsigned wnz = 0;
#pragma unroll 1
    for (int m = 0; m < 16; ++m) {
        unsigned bits = 0;
#pragma unroll 4
        for (int j = 0; j < 32; ++j) {
            int s;
            DP4A_SCORE(m * 32 + j, s);
            if (s <= thr) bits |= (1u << j);
            thr = min(thr, s + twoCh + M);
        }
        s_mask[m * 512 + tid] = bits;   // conflict-free: consecutive tid
        if (bits) wnz |= (1u << m);
    }

    // ---- phase 3: load zr (registers now free), exact rescore from smem ----
    float zr[D_];
#pragma unroll
    for (int i = 0; i < D_; ++i) zr[i] = zc[(size_t)i << 12];

    float bd = 3.402823466e38f;
    int bestk = 0;
    unsigned wm = wnz;
    while (wm) {                           // ascending words
        int m = __ffs(wm) - 1;
        wm &= wm - 1;
        unsigned bits = s_mask[m * 512 + tid];
        while (bits) {                     // ascending bits -> first-min ties
            int j = __ffs(bits) - 1;
            bits &= bits - 1;
            int k = m * 32 + j;
            float dd = exact_dist_sm(zr, A, s_cbf, s_cnf, k);
            if (dd < bd) { bd = dd; bestk = k; }
        }
    }

    if (out_i) out_i[n] = (float)bestk;

    // ---- phase 4: quantized output (fl(z + fl(q-z))) + loss partial ----
    float acc = 0.0f;
    const float4* qr = s_cbf + bestk * 17;
    float* oq = out_q ? out_q + zoff : nullptr;
#pragma unroll
    for (int j = 0; j < 16; ++j) {
        float4 qv = qr[j];
        float d0 = __fsub_rn(qv.x, zr[4 * j + 0]);
        float d1 = __fsub_rn(qv.y, zr[4 * j + 1]);
        float d2 = __fsub_rn(qv.z, zr[4 * j + 2]);
        float d3 = __fsub_rn(qv.w, zr[4 * j + 3]);
        if (oq) {
            oq[(size_t)(4 * j + 0) << 12] = __fadd_rn(zr[4 * j + 0], d0);
            oq[(size_t)(4 * j + 1) << 12] = __fadd_rn(zr[4 * j + 1], d1);
            oq[(size_t)(4 * j + 2) << 12] = __fadd_rn(zr[4 * j + 2], d2);
            oq[(size_t)(4 * j + 3) << 12] = __fadd_rn(zr[4 * j + 3], d3);
        }
        acc = fmaf(d0, d0, acc);
        acc = fmaf(d1, d1, acc);
        acc = fmaf(d2, d2, acc);
        acc = fmaf(d3, d3, acc);
    }
#pragma unroll
    for (int o = 16; o > 0; o >>= 1) acc += __shfl_xor_sync(0xffffffffu, acc, o);
    if (lane == 0) s_wsum[wid] = acc;
    __syncthreads();
    if (tid == 0) {
        float s = 0.0f;
#pragma unroll
        for (int i = 0; i < 16; ++i) s += s_wsum[i];
        g_partial[blockIdx.x] = s;
        __threadfence();
        unsigned int ticket = atomicAdd(&g_count, 1u);
        s_last[0] = (ticket == 255u) ? 1 : 0;
    }
    __syncthreads();

    // ---- last block: deterministic finalize ----
    if (s_last[0]) {
        if (tid < 256) s_rd[tid] = (double)g_partial[tid];
        __syncthreads();
        for (int st = 128; st > 0; st >>= 1) {
            if (tid < st) s_rd[tid] += s_rd[tid + st];
            __syncthreads();
        }
        if (tid == 0) {
            if (loss_ptr) {
                float cl_ = (float)(s_rd[0] / (double)NQ_);
                loss_ptr[0] = __fadd_rn(cl_, __fmul_rn(0.25f, cl_));
            }
            g_count = 0;   // reset for next graph replay
        }
    }
}

// ---------------------------------------------------------------------------
extern "C" void kernel_launch(void* const* d_in, const int* in_sizes, int n_in,
                              void* d_out, int out_size) {
    const float* z  = nullptr;
    const float* cb = nullptr;
    for (int i = 0; i < n_in; ++i) {
        if (in_sizes[i] == NQ_)          z  = (const float*)d_in[i];
        else if (in_sizes[i] == K_ * D_) cb = (const float*)d_in[i];
    }
    if (!z || !cb) return;

    float* out = (float*)d_out;
    float* loss_ptr = nullptr;
    float* q_ptr    = nullptr;
    float* i_ptr    = nullptr;

    if (out_size == 1 + NQ_ + N_) {
        loss_ptr = out; q_ptr = out + 1; i_ptr = out + 1 + NQ_;
    } else if (out_size == NQ_ + N_) {
        q_ptr = out; i_ptr = out + NQ_;
    } else if (out_size == NQ_) {
        q_ptr = out;
    } else if (out_size == N_) {
        i_ptr = out;
    } else if (out_size == 1) {
        loss_ptr = out;
    } else if (out_size > 1 + NQ_ + N_) {
        loss_ptr = out; q_ptr = out + 1; i_ptr = out + 1 + NQ_;
    }

    static bool attr_done = false;
    if (!attr_done) {
        cudaFuncSetAttribute(vq_kernel,
                             cudaFuncAttributeMaxDynamicSharedMemorySize,
                             SM_TOT);
        attr_done = true;
    }

    prep_z_kernel<<<512, 256>>>(z);
    prep_cb1_kernel<<<2, 256>>>(cb);
    prep_cb2_kernel<<<2, 256>>>(cb);
    vq_kernel<<<N_ / 512, 512, SM_TOT>>>(z, cb, q_ptr, i_ptr, loss_ptr);
}

// round 13
// speedup vs baseline: 2.8928x; 1.0288x over previous
#include <cuda_runtime.h>
#include <cstdint>

// Problem constants (fixed by the reference)
#define B_ 32
#define D_ 64
#define T_ 4096
#define K_ 512
#define N_ (B_ * T_)        // 131072 tokens
#define NQ_ (B_ * D_ * T_)  // 8388608 quantized elements

// Scratch (device globals: no allocation allowed)
__device__ unsigned int g_maxz_bits;
__device__ unsigned int g_maxc_bits;
__device__ float        g_cbnorm[K_];
__device__ int2         g_cnsc[K_];            // (cn_int - ch, 2*ch), ch = ceil(sc/2)
__device__ __align__(16) int g_cbimg[K_ * 16];
__device__ float        g_partial[256];
__device__ unsigned int g_count;

// ---------------------------------------------------------------------------
// prep 0: global max |z|
// ---------------------------------------------------------------------------
__global__ void prep_z_kernel(const float* __restrict__ z) {
    const float4* z4 = reinterpret_cast<const float4*>(z);
    float m = 0.0f;
    for (int j = blockIdx.x * blockDim.x + threadIdx.x; j < NQ_ / 4;
         j += gridDim.x * blockDim.x) {
        float4 v = z4[j];
        m = fmaxf(m, fmaxf(fmaxf(fabsf(v.x), fabsf(v.y)),
                           fmaxf(fabsf(v.z), fabsf(v.w))));
    }
#pragma unroll
    for (int o = 16; o > 0; o >>= 1) m = fmaxf(m, __shfl_xor_sync(0xffffffffu, m, o));
    if ((threadIdx.x & 31) == 0) atomicMax(&g_maxz_bits, __float_as_uint(m));
}

// prep 1: exact norms (canonical fmaf order, proven rel_err = 0.0) + max |c|
__global__ void prep_cb1_kernel(const float* __restrict__ cb) {
    int k = blockIdx.x * blockDim.x + threadIdx.x;
    if (k < K_) {
        const float* r = cb + k * D_;
        float a = 0.0f, mx = 0.0f;
#pragma unroll
        for (int i = 0; i < D_; ++i) {
            a = fmaf(r[i], r[i], a);
            mx = fmaxf(mx, fabsf(r[i]));
        }
        g_cbnorm[k] = a;
        atomicMax(&g_maxc_bits, __float_as_uint(mx));
    }
}

// prep 2: int8 image, (cn_int - ch, 2*ch)  [bit-validated rounds 10-12]
__global__ void prep_cb2_kernel(const float* __restrict__ cb) {
    int k = blockIdx.x * blockDim.x + threadIdx.x;
    if (k >= K_) return;
    const float maxz = __uint_as_float(g_maxz_bits);
    const float maxc = __uint_as_float(g_maxc_bits);
    const float inv_sc = (maxc > 0.0f) ? 127.0f / maxc : 0.0f;
    const float* r = cb + k * D_;
    int sa = 0;
#pragma unroll
    for (int j = 0; j < 16; ++j) {
        int b0 = min(127, max(-127, __float2int_rn(r[4 * j + 0] * inv_sc)));
        int b1 = min(127, max(-127, __float2int_rn(r[4 * j + 1] * inv_sc)));
        int b2 = min(127, max(-127, __float2int_rn(r[4 * j + 2] * inv_sc)));
        int b3 = min(127, max(-127, __float2int_rn(r[4 * j + 3] * inv_sc)));
        sa += abs(b0) + abs(b1) + abs(b2) + abs(b3);
        g_cbimg[k * 16 + j] = (b0 & 0xFF) | ((b1 & 0xFF) << 8) |
                              ((b2 & 0xFF) << 16) | ((b3 & 0xFF) << 24);
    }
    const float denom = 2.0f * (maxz * (1.0f / 127.0f)) * (maxc * (1.0f / 127.0f));
    float v = (denom > 0.0f) ? g_cbnorm[k] / denom : 0.0f;
    int cni = __float2int_rn(fminf(fmaxf(v, -2.0e9f), 2.0e9f));
    int ch  = (sa + 1) >> 1;                    // ceil(sc/2): conservative
    g_cnsc[k] = make_int2(cni - ch, 2 * ch);
}

// dual-token dp4a score block: s0/s1 = (cn_int - ch) - idot (seeded)
#define DP4A_SCORE2(k, sOut0, sOut1) do {                                 \
    int4 c0 = s_img[4 * (k) + 0], c1 = s_img[4 * (k) + 1];                \
    int4 c2 = s_img[4 * (k) + 2], c3 = s_img[4 * (k) + 3];                \
    int2 cs = s_cnsc[(k)];                                                \
    int a0 = cs.x, a1 = 0, a2 = 0, a3 = 0;                                \
    int b0 = cs.x, b1 = 0, b2 = 0, b3 = 0;                                \
    a0 = __dp4a(zp0[0],  c0.x, a0);  b0 = __dp4a(zp1[0],  c0.x, b0);      \
    a1 = __dp4a(zp0[1],  c0.y, a1);  b1 = __dp4a(zp1[1],  c0.y, b1);      \
    a2 = __dp4a(zp0[2],  c0.z, a2);  b2 = __dp4a(zp1[2],  c0.z, b2);      \
    a3 = __dp4a(zp0[3],  c0.w, a3);  b3 = __dp4a(zp1[3],  c0.w, b3);      \
    a0 = __dp4a(zp0[4],  c1.x, a0);  b0 = __dp4a(zp1[4],  c1.x, b0);      \
    a1 = __dp4a(zp0[5],  c1.y, a1);  b1 = __dp4a(zp1[5],  c1.y, b1);      \
    a2 = __dp4a(zp0[6],  c1.z, a2);  b2 = __dp4a(zp1[6],  c1.z, b2);      \
    a3 = __dp4a(zp0[7],  c1.w, a3);  b3 = __dp4a(zp1[7],  c1.w, b3);      \
    a0 = __dp4a(zp0[8],  c2.x, a0);  b0 = __dp4a(zp1[8],  c2.x, b0);      \
    a1 = __dp4a(zp0[9],  c2.y, a1);  b1 = __dp4a(zp1[9],  c2.y, b1);      \
    a2 = __dp4a(zp0[10], c2.z, a2);  b2 = __dp4a(zp1[10], c2.z, b2);      \
    a3 = __dp4a(zp0[11], c2.w, a3);  b3 = __dp4a(zp1[11], c2.w, b3);      \
    a0 = __dp4a(zp0[12], c3.x, a0);  b0 = __dp4a(zp1[12], c3.x, b0);      \
    a1 = __dp4a(zp0[13], c3.y, a1);  b1 = __dp4a(zp1[13], c3.y, b1);      \
    a2 = __dp4a(zp0[14], c3.z, a2);  b2 = __dp4a(zp1[14], c3.z, b2);      \
    a3 = __dp4a(zp0[15], c3.w, a3);  b3 = __dp4a(zp1[15], c3.w, b3);      \
    (sOut0) = (a0 + a1) + (a2 + a3);                                      \
    (sOut1) = (b0 + b1) + (b2 + b3);                                      \
    twoCh = cs.y;                                                         \
} while (0)

// ---------------------------------------------------------------------------
// Exact fp32 distance from PADDED smem codebook (row stride 17 float4 units).
// Bit-identical to the proven round-0 formula.
// ---------------------------------------------------------------------------
__device__ __forceinline__ float exact_dist_sm(const float* zr, float A,
                                               const float4* __restrict__ cbf,
                                               const float* __restrict__ cnf,
                                               int k) {
    const float4* cp = cbf + k * 17;
    float s0 = 0.f, s1 = 0.f, s2 = 0.f, s3 = 0.f;
#pragma unroll
    for (int i = 0; i < 16; ++i) {
        float4 c = cp[i];
        s0 = fmaf(zr[4 * i + 0], c.x, s0);
        s1 = fmaf(zr[4 * i + 1], c.y, s1);
        s2 = fmaf(zr[4 * i + 2], c.z, s2);
        s3 = fmaf(zr[4 * i + 3], c.w, s3);
    }
    float dot = __fadd_rn(__fadd_rn(s0, s1), __fadd_rn(s2, s3));
    return __fadd_rn(__fadd_rn(A, cnf[k]), -__fmul_rn(2.0f, dot));
}

// ---------------------------------------------------------------------------
// fused VQ kernel. 256 thd, 2 tokens/thread, 1 block/SM, grid 256 (512 tok/blk).
// ---------------------------------------------------------------------------
#define SM_IMG   0                            // 2048 int4        =  32768
#define SM_CNSC  32768                        // 512 int2         =   4096
#define SM_CNF   36864                        // 512 float        =   2048
#define SM_CBF   38912                        // 512*17 float4    = 139264
#define SM_MASK  178176                       // 16*512 uint      =  32768
#define SM_WSUM  210944                       // 8 float (+pad)   =     64
#define SM_RD    211008                       // 256 double       =   2048
#define SM_LAST  213056                       // int (+pad)       =     16
#define SM_TOT   213072

__global__ __launch_bounds__(256, 1)
void vq_kernel(const float* __restrict__ z,
               const float* __restrict__ cb,
               float* __restrict__ out_q,
               float* __restrict__ out_i,
               float* __restrict__ loss_ptr) {
    extern __shared__ char sm[];
    int4*     s_img  = reinterpret_cast<int4*>(sm + SM_IMG);
    int2*     s_cnsc = reinterpret_cast<int2*>(sm + SM_CNSC);
    float*    s_cnf  = reinterpret_cast<float*>(sm + SM_CNF);
    float4*   s_cbf  = reinterpret_cast<float4*>(sm + SM_CBF);
    unsigned* s_mask = reinterpret_cast<unsigned*>(sm + SM_MASK);
    float*    s_wsum = reinterpret_cast<float*>(sm + SM_WSUM);
    double*   s_rd   = reinterpret_cast<double*>(sm + SM_RD);
    int*      s_last = reinterpret_cast<int*>(sm + SM_LAST);

    const int tid  = threadIdx.x;
    const int wid  = tid >> 5;
    const int lane = tid & 31;

    // ---- stage: int8 image, (cnlo,2ch), fp32 cn, padded fp32 codebook ----
    {
        const int4* src = reinterpret_cast<const int4*>(g_cbimg);
#pragma unroll
        for (int i = tid; i < K_ * 4; i += 256) s_img[i] = src[i];
#pragma unroll
        for (int i = tid; i < K_; i += 256) {
            s_cnsc[i] = g_cnsc[i];
            s_cnf[i]  = g_cbnorm[i];
        }
        const float4* cb4 = reinterpret_cast<const float4*>(cb);
#pragma unroll
        for (int i = tid; i < K_ * 16; i += 256)
            s_cbf[(i >> 4) * 17 + (i & 15)] = cb4[i];
    }

    // ---- phase 1: stream both tokens (low reg footprint) ----
    const int nbase = blockIdx.x * 512;
    const int bidx  = nbase >> 12;
    const float* zb = z + ((size_t)bidx << 18);
    const int t0 = (nbase & 4095) + tid;       // token 0 column
    const int t1 = t0 + 256;                   // token 1 column

    const float maxz = __uint_as_float(g_maxz_bits);
    const float inv_sz = (maxz > 0.0f) ? 127.0f / maxz : 0.0f;
    float A0 = 0.0f, A1 = 0.0f;
    int zp0[16], zp1[16];
    int sabs0 = 0, sabs1 = 0;
#pragma unroll
    for (int j = 0; j < 16; ++j) {
        int p0 = 0, p1 = 0;
#pragma unroll
        for (int q = 0; q < 4; ++q) {
            float x0 = zb[((size_t)(4 * j + q) << 12) + t0];
            float x1 = zb[((size_t)(4 * j + q) << 12) + t1];
            A0 = fmaf(x0, x0, A0);     // canonical i = 0..63 order per token
            A1 = fmaf(x1, x1, A1);
            int b0 = min(127, max(-127, __float2int_rn(x0 * inv_sz)));
            int b1 = min(127, max(-127, __float2int_rn(x1 * inv_sz)));
            sabs0 += abs(b0);
            sabs1 += abs(b1);
            p0 |= ((-b0) & 0xFF) << (q * 8);
            p1 |= ((-b1) & 0xFF) << (q * 8);
        }
        zp0[j] = p0;
        zp1[j] = p1;
    }

    // sound margins (bit-validated rounds 10-12)
    const float maxc  = __uint_as_float(g_maxc_bits);
    const float denom = 2.0f * (maxz * (1.0f / 127.0f)) * (maxc * (1.0f / 127.0f));
    const float slack_f = (denom > 0.0f) ? 2.0e-4f / denom : 4.0e9f;
    const int   slack   = (slack_f < 1.0e9f) ? ((int)slack_f + 2) : (1 << 27);
    long long ml0 = (long long)sabs0 + 2LL * slack + 128;
    long long ml1 = (long long)sabs1 + 2LL * slack + 128;
    const int M0 = (int)((ml0 < (1LL << 29)) ? ml0 : (1LL << 29));
    const int M1 = (int)((ml1 < (1LL << 29)) ? ml1 : (1LL << 29));

    __syncthreads();

    // ---- phase 2a: pre-pass over 64 strided codes -> warm thresholds ----
    int twoCh;
    int m00 = 0x7FFFFFFF, m01 = 0x7FFFFFFF;
#pragma unroll 4
    for (int j = 0; j < 64; ++j) {
        int s0, s1;
        DP4A_SCORE2(j * 8, s0, s1);
        m00 = min(m00, s0 + twoCh);
        m01 = min(m01, s1 + twoCh);
    }
    int thr0 = m00 + M0;
    int thr1 = m01 + M1;

    // ---- phase 2b: full dual-token screen -> bitmasks + word summaries ----
    unsigned wnz0 = 0, wnz1 = 0;
#pragma unroll 1
    for (int m = 0; m < 16; ++m) {
        unsigned bits0 = 0, bits1 = 0;
#pragma unroll 4
        for (int j = 0; j < 32; ++j) {
            int s0, s1;
            DP4A_SCORE2(m * 32 + j, s0, s1);
            if (s0 <= thr0) bits0 |= (1u << j);
            thr0 = min(thr0, s0 + twoCh + M0);
            if (s1 <= thr1) bits1 |= (1u << j);
            thr1 = min(thr1, s1 + twoCh + M1);
        }
        s_mask[m * 512 + tid]       = bits0;
        s_mask[m * 512 + 256 + tid] = bits1;
        if (bits0) wnz0 |= (1u << m);
        if (bits1) wnz1 |= (1u << m);
    }

    // ---- phases 3+4 per token: exact rescore, output, loss ----
    float acc = 0.0f;
#pragma unroll 1
    for (int t = 0; t < 2; ++t) {
        const int tcol = (t == 0) ? t0 : t1;
        const int tl   = (t == 0) ? tid : (256 + tid);
        unsigned wm    = (t == 0) ? wnz0 : wnz1;
        const float A  = (t == 0) ? A0 : A1;
        const float* zc = zb + tcol;

        float zr[D_];
#pragma unroll
        for (int i = 0; i < D_; ++i) zr[i] = zc[(size_t)i << 12];

        float bd = 3.402823466e38f;
        int bestk = 0;
        while (wm) {                       // ascending words
            int m = __ffs(wm) - 1;
            wm &= wm - 1;
            unsigned bits = s_mask[m * 512 + tl];
            while (bits) {                 // ascending bits -> first-min ties
                int j = __ffs(bits) - 1;
                bits &= bits - 1;
                int k = m * 32 + j;
                float dd = exact_dist_sm(zr, A, s_cbf, s_cnf, k);
                if (dd < bd) { bd = dd; bestk = k; }
            }
        }

        const int n = (bidx << 12) + tcol;
        if (out_i) out_i[n] = (float)bestk;

        const float4* qr = s_cbf + bestk * 17;
        float* oq = out_q ? out_q + ((size_t)bidx << 18) + tcol : nullptr;
#pragma unroll
        for (int j = 0; j < 16; ++j) {
            float4 qv = qr[j];
            float d0 = __fsub_rn(qv.x, zr[4 * j + 0]);
            float d1 = __fsub_rn(qv.y, zr[4 * j + 1]);
            float d2 = __fsub_rn(qv.z, zr[4 * j + 2]);
            float d3 = __fsub_rn(qv.w, zr[4 * j + 3]);
            if (oq) {
                oq[(size_t)(4 * j + 0) << 12] = __fadd_rn(zr[4 * j + 0], d0);
                oq[(size_t)(4 * j + 1) << 12] = __fadd_rn(zr[4 * j + 1], d1);
                oq[(size_t)(4 * j + 2) << 12] = __fadd_rn(zr[4 * j + 2], d2);
                oq[(size_t)(4 * j + 3) << 12] = __fadd_rn(zr[4 * j + 3], d3);
            }
            acc = fmaf(d0, d0, acc);
            acc = fmaf(d1, d1, acc);
            acc = fmaf(d2, d2, acc);
            acc = fmaf(d3, d3, acc);
        }
    }

#pragma unroll
    for (int o = 16; o > 0; o >>= 1) acc += __shfl_xor_sync(0xffffffffu, acc, o);
    if (lane == 0) s_wsum[wid] = acc;
    __syncthreads();
    if (tid == 0) {
        float s = 0.0f;
#pragma unroll
        for (int i = 0; i < 8; ++i) s += s_wsum[i];
        g_partial[blockIdx.x] = s;
        __threadfence();
        unsigned int ticket = atomicAdd(&g_count, 1u);
        s_last[0] = (ticket == 255u) ? 1 : 0;
    }
    __syncthreads();

    // ---- last block: deterministic finalize ----
    if (s_last[0]) {
        if (tid < 256) s_rd[tid] = (double)g_partial[tid];
        __syncthreads();
        for (int st = 128; st > 0; st >>= 1) {
            if (tid < st) s_rd[tid] += s_rd[tid + st];
            __syncthreads();
        }
        if (tid == 0) {
            if (loss_ptr) {
                float cl_ = (float)(s_rd[0] / (double)NQ_);
                loss_ptr[0] = __fadd_rn(cl_, __fmul_rn(0.25f, cl_));
            }
            g_count = 0;   // reset for next graph replay
        }
    }
}

// ---------------------------------------------------------------------------
extern "C" void kernel_launch(void* const* d_in, const int* in_sizes, int n_in,
                              void* d_out, int out_size) {
    const float* z  = nullptr;
    const float* cb = nullptr;
    for (int i = 0; i < n_in; ++i) {
        if (in_sizes[i] == NQ_)          z  = (const float*)d_in[i];
        else if (in_sizes[i] == K_ * D_) cb = (const float*)d_in[i];
    }
    if (!z || !cb) return;

    float* out = (float*)d_out;
    float* loss_ptr = nullptr;
    float* q_ptr    = nullptr;
    float* i_ptr    = nullptr;

    if (out_size == 1 + NQ_ + N_) {
        loss_ptr = out; q_ptr = out + 1; i_ptr = out + 1 + NQ_;
    } else if (out_size == NQ_ + N_) {
        q_ptr = out; i_ptr = out + NQ_;
    } else if (out_size == NQ_) {
        q_ptr = out;
    } else if (out_size == N_) {
        i_ptr = out;
    } else if (out_size == 1) {
        loss_ptr = out;
    } else if (out_size > 1 + NQ_ + N_) {
        loss_ptr = out; q_ptr = out + 1; i_ptr = out + 1 + NQ_;
    }

    static bool attr_done = false;
    if (!attr_done) {
        cudaFuncSetAttribute(vq_kernel,
                             cudaFuncAttributeMaxDynamicSharedMemorySize,
                             SM_TOT);
        attr_done = true;
    }

    prep_z_kernel<<<512, 256>>>(z);
    prep_cb1_kernel<<<2, 256>>>(cb);
    prep_cb2_kernel<<<2, 256>>>(cb);
    vq_kernel<<<N_ / 512, 256, SM_TOT>>>(z, cb, q_ptr, i_ptr, loss_ptr);
}

// round 14
// speedup vs baseline: 2.9491x; 1.0195x over previous
#include <cuda_runtime.h>
#include <cstdint>

// Problem constants (fixed by the reference)
#define B_ 32
#define D_ 64
#define T_ 4096
#define K_ 512
#define N_ (B_ * T_)        // 131072 tokens
#define NQ_ (B_ * D_ * T_)  // 8388608 quantized elements
#define NCHUNK_ 256         // 512 tokens per chunk
#define NBLK_ 148           // persistent blocks (1/SM)

// Scratch (device globals: no allocation allowed)
__device__ unsigned int g_maxz_bits;
__device__ unsigned int g_maxc_bits;
__device__ float        g_cbnorm[K_];
__device__ int2         g_cnsc[K_];            // (cn_int - ch, 2*ch), ch = ceil(sc/2)
__device__ __align__(16) int g_cbimg[K_ * 16];
__device__ float        g_partial[NCHUNK_];
__device__ unsigned int g_count;
__device__ unsigned int g_chunk;

// ---------------------------------------------------------------------------
// prep 0: global max |z|
// ---------------------------------------------------------------------------
__global__ void prep_z_kernel(const float* __restrict__ z) {
    const float4* z4 = reinterpret_cast<const float4*>(z);
    float m = 0.0f;
    for (int j = blockIdx.x * blockDim.x + threadIdx.x; j < NQ_ / 4;
         j += gridDim.x * blockDim.x) {
        float4 v = z4[j];
        m = fmaxf(m, fmaxf(fmaxf(fabsf(v.x), fabsf(v.y)),
                           fmaxf(fabsf(v.z), fabsf(v.w))));
    }
#pragma unroll
    for (int o = 16; o > 0; o >>= 1) m = fmaxf(m, __shfl_xor_sync(0xffffffffu, m, o));
    if ((threadIdx.x & 31) == 0) atomicMax(&g_maxz_bits, __float_as_uint(m));
}

// prep 1: exact norms (canonical fmaf order, proven rel_err = 0.0) + max |c|
__global__ void prep_cb1_kernel(const float* __restrict__ cb) {
    int k = blockIdx.x * blockDim.x + threadIdx.x;
    if (k < K_) {
        const float* r = cb + k * D_;
        float a = 0.0f, mx = 0.0f;
#pragma unroll
        for (int i = 0; i < D_; ++i) {
            a = fmaf(r[i], r[i], a);
            mx = fmaxf(mx, fabsf(r[i]));
        }
        g_cbnorm[k] = a;
        atomicMax(&g_maxc_bits, __float_as_uint(mx));
    }
}

// prep 2: int8 image, (cn_int - ch, 2*ch)  [bit-validated rounds 10-13]
__global__ void prep_cb2_kernel(const float* __restrict__ cb) {
    int k = blockIdx.x * blockDim.x + threadIdx.x;
    if (k >= K_) return;
    const float maxz = __uint_as_float(g_maxz_bits);
    const float maxc = __uint_as_float(g_maxc_bits);
    const float inv_sc = (maxc > 0.0f) ? 127.0f / maxc : 0.0f;
    const float* r = cb + k * D_;
    int sa = 0;
#pragma unroll
    for (int j = 0; j < 16; ++j) {
        int b0 = min(127, max(-127, __float2int_rn(r[4 * j + 0] * inv_sc)));
        int b1 = min(127, max(-127, __float2int_rn(r[4 * j + 1] * inv_sc)));
        int b2 = min(127, max(-127, __float2int_rn(r[4 * j + 2] * inv_sc)));
        int b3 = min(127, max(-127, __float2int_rn(r[4 * j + 3] * inv_sc)));
        sa += abs(b0) + abs(b1) + abs(b2) + abs(b3);
        g_cbimg[k * 16 + j] = (b0 & 0xFF) | ((b1 & 0xFF) << 8) |
                              ((b2 & 0xFF) << 16) | ((b3 & 0xFF) << 24);
    }
    const float denom = 2.0f * (maxz * (1.0f / 127.0f)) * (maxc * (1.0f / 127.0f));
    float v = (denom > 0.0f) ? g_cbnorm[k] / denom : 0.0f;
    int cni = __float2int_rn(fminf(fmaxf(v, -2.0e9f), 2.0e9f));
    int ch  = (sa + 1) >> 1;                    // ceil(sc/2): conservative
    g_cnsc[k] = make_int2(cni - ch, 2 * ch);
}

// dual-token dp4a score block: s0/s1 = (cn_int - ch) - idot (seeded)
#define DP4A_SCORE2(k, sOut0, sOut1) do {                                 \
    int4 c0 = s_img[4 * (k) + 0], c1 = s_img[4 * (k) + 1];                \
    int4 c2 = s_img[4 * (k) + 2], c3 = s_img[4 * (k) + 3];                \
    int2 cs = s_cnsc[(k)];                                                \
    int a0 = cs.x, a1 = 0, a2 = 0, a3 = 0;                                \
    int b0 = cs.x, b1 = 0, b2 = 0, b3 = 0;                                \
    a0 = __dp4a(zp0[0],  c0.x, a0);  b0 = __dp4a(zp1[0],  c0.x, b0);      \
    a1 = __dp4a(zp0[1],  c0.y, a1);  b1 = __dp4a(zp1[1],  c0.y, b1);      \
    a2 = __dp4a(zp0[2],  c0.z, a2);  b2 = __dp4a(zp1[2],  c0.z, b2);      \
    a3 = __dp4a(zp0[3],  c0.w, a3);  b3 = __dp4a(zp1[3],  c0.w, b3);      \
    a0 = __dp4a(zp0[4],  c1.x, a0);  b0 = __dp4a(zp1[4],  c1.x, b0);      \
    a1 = __dp4a(zp0[5],  c1.y, a1);  b1 = __dp4a(zp1[5],  c1.y, b1);      \
    a2 = __dp4a(zp0[6],  c1.z, a2);  b2 = __dp4a(zp1[6],  c1.z, b2);      \
    a3 = __dp4a(zp0[7],  c1.w, a3);  b3 = __dp4a(zp1[7],  c1.w, b3);      \
    a0 = __dp4a(zp0[8],  c2.x, a0);  b0 = __dp4a(zp1[8],  c2.x, b0);      \
    a1 = __dp4a(zp0[9],  c2.y, a1);  b1 = __dp4a(zp1[9],  c2.y, b1);      \
    a2 = __dp4a(zp0[10], c2.z, a2);  b2 = __dp4a(zp1[10], c2.z, b2);      \
    a3 = __dp4a(zp0[11], c2.w, a3);  b3 = __dp4a(zp1[11], c2.w, b3);      \
    a0 = __dp4a(zp0[12], c3.x, a0);  b0 = __dp4a(zp1[12], c3.x, b0);      \
    a1 = __dp4a(zp0[13], c3.y, a1);  b1 = __dp4a(zp1[13], c3.y, b1);      \
    a2 = __dp4a(zp0[14], c3.z, a2);  b2 = __dp4a(zp1[14], c3.z, b2);      \
    a3 = __dp4a(zp0[15], c3.w, a3);  b3 = __dp4a(zp1[15], c3.w, b3);      \
    (sOut0) = (a0 + a1) + (a2 + a3);                                      \
    (sOut1) = (b0 + b1) + (b2 + b3);                                      \
    twoCh = cs.y;                                                         \
} while (0)

// ---------------------------------------------------------------------------
// Exact fp32 distance from PADDED smem codebook (row stride 17 float4 units).
// Bit-identical to the proven round-0 formula.
// ---------------------------------------------------------------------------
__device__ __forceinline__ float exact_dist_sm(const float* zr, float A,
                                               const float4* __restrict__ cbf,
                                               const float* __restrict__ cnf,
                                               int k) {
    const float4* cp = cbf + k * 17;
    float s0 = 0.f, s1 = 0.f, s2 = 0.f, s3 = 0.f;
#pragma unroll
    for (int i = 0; i < 16; ++i) {
        float4 c = cp[i];
        s0 = fmaf(zr[4 * i + 0], c.x, s0);
        s1 = fmaf(zr[4 * i + 1], c.y, s1);
        s2 = fmaf(zr[4 * i + 2], c.z, s2);
        s3 = fmaf(zr[4 * i + 3], c.w, s3);
    }
    float dot = __fadd_rn(__fadd_rn(s0, s1), __fadd_rn(s2, s3));
    return __fadd_rn(__fadd_rn(A, cnf[k]), -__fmul_rn(2.0f, dot));
}

// ---------------------------------------------------------------------------
// persistent fused VQ kernel. 256 thd, 2 tokens/thread, grid 148 (1/SM),
// atomic chunk stealing over 256 chunks of 512 tokens.
// ---------------------------------------------------------------------------
#define SM_IMG   0                            // 2048 int4        =  32768
#define SM_CNSC  32768                        // 512 int2         =   4096
#define SM_CNF   36864                        // 512 float        =   2048
#define SM_CBF   38912                        // 512*17 float4    = 139264
#define SM_MASK  178176                       // 16*512 uint      =  32768
#define SM_WSUM  210944                       // 8 float (+pad)   =     64
#define SM_RD    211008                       // 256 double       =   2048
#define SM_LAST  213056                       // int              =      4
#define SM_CHNK  213060                       // int (+pad)       =     12
#define SM_TOT   213072

__global__ __launch_bounds__(256, 1)
void vq_kernel(const float* __restrict__ z,
               const float* __restrict__ cb,
               float* __restrict__ out_q,
               float* __restrict__ out_i,
               float* __restrict__ loss_ptr) {
    extern __shared__ char sm[];
    int4*     s_img  = reinterpret_cast<int4*>(sm + SM_IMG);
    int2*     s_cnsc = reinterpret_cast<int2*>(sm + SM_CNSC);
    float*    s_cnf  = reinterpret_cast<float*>(sm + SM_CNF);
    float4*   s_cbf  = reinterpret_cast<float4*>(sm + SM_CBF);
    unsigned* s_mask = reinterpret_cast<unsigned*>(sm + SM_MASK);
    float*    s_wsum = reinterpret_cast<float*>(sm + SM_WSUM);
    double*   s_rd   = reinterpret_cast<double*>(sm + SM_RD);
    int*      s_last = reinterpret_cast<int*>(sm + SM_LAST);
    int*      s_chnk = reinterpret_cast<int*>(sm + SM_CHNK);

    const int tid  = threadIdx.x;
    const int wid  = tid >> 5;
    const int lane = tid & 31;

    // ---- stage ONCE: int8 image, (cnlo,2ch), fp32 cn, padded fp32 codebook
    {
        const int4* src = reinterpret_cast<const int4*>(g_cbimg);
#pragma unroll
        for (int i = tid; i < K_ * 4; i += 256) s_img[i] = src[i];
#pragma unroll
        for (int i = tid; i < K_; i += 256) {
            s_cnsc[i] = g_cnsc[i];
            s_cnf[i]  = g_cbnorm[i];
        }
        const float4* cb4 = reinterpret_cast<const float4*>(cb);
#pragma unroll
        for (int i = tid; i < K_ * 16; i += 256)
            s_cbf[(i >> 4) * 17 + (i & 15)] = cb4[i];
    }

    const float maxz = __uint_as_float(g_maxz_bits);
    const float inv_sz = (maxz > 0.0f) ? 127.0f / maxz : 0.0f;
    const float maxc  = __uint_as_float(g_maxc_bits);
    const float denom = 2.0f * (maxz * (1.0f / 127.0f)) * (maxc * (1.0f / 127.0f));
    const float slack_f = (denom > 0.0f) ? 2.0e-4f / denom : 4.0e9f;
    const int   slack   = (slack_f < 1.0e9f) ? ((int)slack_f + 2) : (1 << 27);

    // ---- persistent chunk-stealing loop ----
    for (;;) {
        __syncthreads();                      // protect s_mask/s_wsum reuse
        if (tid == 0) s_chnk[0] = (int)atomicAdd(&g_chunk, 1u);
        __syncthreads();
        const int chunk = s_chnk[0];
        if (chunk >= NCHUNK_) break;

        // ---- phase 1: stream both tokens (low reg footprint) ----
        const int nbase = chunk * 512;
        const int bidx  = nbase >> 12;
        const float* zb = z + ((size_t)bidx << 18);
        const int t0 = (nbase & 4095) + tid;   // token 0 column
        const int t1 = t0 + 256;               // token 1 column

        float A0 = 0.0f, A1 = 0.0f;
        int zp0[16], zp1[16];
        int sabs0 = 0, sabs1 = 0;
#pragma unroll
        for (int j = 0; j < 16; ++j) {
            int p0 = 0, p1 = 0;
#pragma unroll
            for (int q = 0; q < 4; ++q) {
                float x0 = zb[((size_t)(4 * j + q) << 12) + t0];
                float x1 = zb[((size_t)(4 * j + q) << 12) + t1];
                A0 = fmaf(x0, x0, A0);  // canonical i = 0..63 order per token
                A1 = fmaf(x1, x1, A1);
                int b0 = min(127, max(-127, __float2int_rn(x0 * inv_sz)));
                int b1 = min(127, max(-127, __float2int_rn(x1 * inv_sz)));
                sabs0 += abs(b0);
                sabs1 += abs(b1);
                p0 |= ((-b0) & 0xFF) << (q * 8);
                p1 |= ((-b1) & 0xFF) << (q * 8);
            }
            zp0[j] = p0;
            zp1[j] = p1;
        }

        long long ml0 = (long long)sabs0 + 2LL * slack + 128;
        long long ml1 = (long long)sabs1 + 2LL * slack + 128;
        const int M0 = (int)((ml0 < (1LL << 29)) ? ml0 : (1LL << 29));
        const int M1 = (int)((ml1 < (1LL << 29)) ? ml1 : (1LL << 29));

        // ---- phase 2a: warm-up prepass (64 strided codes) ----
        int twoCh;
        int m00 = 0x7FFFFFFF, m01 = 0x7FFFFFFF;
#pragma unroll 4
        for (int j = 0; j < 64; ++j) {
            int s0, s1;
            DP4A_SCORE2(j * 8, s0, s1);
            m00 = min(m00, s0 + twoCh);
            m01 = min(m01, s1 + twoCh);
        }
        int thr0 = m00 + M0;
        int thr1 = m01 + M1;

        // ---- phase 2b: full dual-token screen -> bitmasks + summaries ----
        unsigned wnz0 = 0, wnz1 = 0;
#pragma unroll 1
        for (int m = 0; m < 16; ++m) {
            unsigned bits0 = 0, bits1 = 0;
#pragma unroll 4
            for (int j = 0; j < 32; ++j) {
                int s0, s1;
                DP4A_SCORE2(m * 32 + j, s0, s1);
                if (s0 <= thr0) bits0 |= (1u << j);
                thr0 = min(thr0, s0 + twoCh + M0);
                if (s1 <= thr1) bits1 |= (1u << j);
                thr1 = min(thr1, s1 + twoCh + M1);
            }
            s_mask[m * 512 + tid]       = bits0;
            s_mask[m * 512 + 256 + tid] = bits1;
            if (bits0) wnz0 |= (1u << m);
            if (bits1) wnz1 |= (1u << m);
        }

        // ---- phases 3+4 per token: exact rescore, output, loss ----
        float acc = 0.0f;
#pragma unroll 1
        for (int t = 0; t < 2; ++t) {
            const int tcol = (t == 0) ? t0 : t1;
            const int tl   = (t == 0) ? tid : (256 + tid);
            unsigned wm    = (t == 0) ? wnz0 : wnz1;
            const float A  = (t == 0) ? A0 : A1;
            const float* zc = zb + tcol;

            float zr[D_];
#pragma unroll
            for (int i = 0; i < D_; ++i) zr[i] = zc[(size_t)i << 12];

            float bd = 3.402823466e38f;
            int bestk = 0;
            while (wm) {                       // ascending words
                int m = __ffs(wm) - 1;
                wm &= wm - 1;
                unsigned bits = s_mask[m * 512 + tl];
                while (bits) {                 // ascending bits: first-min ties
                    int j = __ffs(bits) - 1;
                    bits &= bits - 1;
                    int k = m * 32 + j;
                    float dd = exact_dist_sm(zr, A, s_cbf, s_cnf, k);
                    if (dd < bd) { bd = dd; bestk = k; }
                }
            }

            const int n = (bidx << 12) + tcol;
            if (out_i) out_i[n] = (float)bestk;

            const float4* qr = s_cbf + bestk * 17;
            float* oq = out_q ? out_q + ((size_t)bidx << 18) + tcol : nullptr;
#pragma unroll
            for (int j = 0; j < 16; ++j) {
                float4 qv = qr[j];
                float d0 = __fsub_rn(qv.x, zr[4 * j + 0]);
                float d1 = __fsub_rn(qv.y, zr[4 * j + 1]);
                float d2 = __fsub_rn(qv.z, zr[4 * j + 2]);
                float d3 = __fsub_rn(qv.w, zr[4 * j + 3]);
                if (oq) {
                    oq[(size_t)(4 * j + 0) << 12] = __fadd_rn(zr[4 * j + 0], d0);
                    oq[(size_t)(4 * j + 1) << 12] = __fadd_rn(zr[4 * j + 1], d1);
                    oq[(size_t)(4 * j + 2) << 12] = __fadd_rn(zr[4 * j + 2], d2);
                    oq[(size_t)(4 * j + 3) << 12] = __fadd_rn(zr[4 * j + 3], d3);
                }
                acc = fmaf(d0, d0, acc);
                acc = fmaf(d1, d1, acc);
                acc = fmaf(d2, d2, acc);
                acc = fmaf(d3, d3, acc);
            }
        }

        // ---- per-chunk loss partial (deterministic per chunk) ----
#pragma unroll
        for (int o = 16; o > 0; o >>= 1)
            acc += __shfl_xor_sync(0xffffffffu, acc, o);
        if (lane == 0) s_wsum[wid] = acc;
        __syncthreads();
        if (tid == 0) {
            float s = 0.0f;
#pragma unroll
            for (int i = 0; i < 8; ++i) s += s_wsum[i];
            g_partial[chunk] = s;
        }
    }

    // ---- completion ticket ----
    if (tid == 0) {
        __threadfence();
        unsigned int ticket = atomicAdd(&g_count, 1u);
        s_last[0] = (ticket == (NBLK_ - 1)) ? 1 : 0;
    }
    __syncthreads();

    // ---- last block: deterministic finalize (same tree as round 13) ----
    if (s_last[0]) {
        if (tid < 256) s_rd[tid] = (double)g_partial[tid];
        __syncthreads();
        for (int st = 128; st > 0; st >>= 1) {
            if (tid < st) s_rd[tid] += s_rd[tid + st];
            __syncthreads();
        }
        if (tid == 0) {
            if (loss_ptr) {
                float cl_ = (float)(s_rd[0] / (double)NQ_);
                loss_ptr[0] = __fadd_rn(cl_, __fmul_rn(0.25f, cl_));
            }
            g_count = 0;   // reset for next graph replay
            g_chunk = 0;
        }
    }
}

// ---------------------------------------------------------------------------
extern "C" void kernel_launch(void* const* d_in, const int* in_sizes, int n_in,
                              void* d_out, int out_size) {
    const float* z  = nullptr;
    const float* cb = nullptr;
    for (int i = 0; i < n_in; ++i) {
        if (in_sizes[i] == NQ_)          z  = (const float*)d_in[i];
        else if (in_sizes[i] == K_ * D_) cb = (const float*)d_in[i];
    }
    if (!z || !cb) return;

    float* out = (float*)d_out;
    float* loss_ptr = nullptr;
    float* q_ptr    = nullptr;
    float* i_ptr    = nullptr;

    if (out_size == 1 + NQ_ + N_) {
        loss_ptr = out; q_ptr = out + 1; i_ptr = out + 1 + NQ_;
    } else if (out_size == NQ_ + N_) {
        q_ptr = out; i_ptr = out + NQ_;
    } else if (out_size == NQ_) {
        q_ptr = out;
    } else if (out_size == N_) {
        i_ptr = out;
    } else if (out_size == 1) {
        loss_ptr = out;
    } else if (out_size > 1 + NQ_ + N_) {
        loss_ptr = out; q_ptr = out + 1; i_ptr = out + 1 + NQ_;
    }

    static bool attr_done = false;
    if (!attr_done) {
        cudaFuncSetAttribute(vq_kernel,
                             cudaFuncAttributeMaxDynamicSharedMemorySize,
                             SM_TOT);
        attr_done = true;
    }

    prep_z_kernel<<<512, 256>>>(z);
    prep_cb1_kernel<<<2, 256>>>(cb);
    prep_cb2_kernel<<<2, 256>>>(cb);
    vq_kernel<<<NBLK_, 256, SM_TOT>>>(z, cb, q_ptr, i_ptr, loss_ptr);
}